// round 14
// baseline (speedup 1.0000x reference)
#include <cuda_runtime.h>
#include <cuda_fp16.h>
#include <math.h>
#include <stdint.h>

#define NG 50000
#define NS 10000
#define EG 800000
#define ES 160000

// ---- scratch layout (float-indexed; half arrays alias 2 halfs per float) ----
static const size_t H0_G  = 0;         // NG*64 halfs = 1.6M floats
static const size_t H0_S  = 1600000;   // NS*64 halfs
static const size_t AGG_G = 2000000;   // NG*128 halfs max
static const size_t AGG_S = 5200000;
static const size_t X1_G  = 6000000;   // NG*128 halfs
static const size_t X1_S  = 9200000;
static const size_t X2_G  = 10000000;  // NG*256 halfs
static const size_t X2_S  = 16400000;
static const size_t X3_G  = 18000000;  // NG*384 halfs
static const size_t X3_S  = 27600000;
static const size_t POOL  = 30000000;  // 2*8*192 floats
static const size_t CNTO  = 30003072;  // 16 floats
static const size_t DEG_G = 30003104;  // ints
static const size_t DEG_S = 30053105;
static const size_t PTR_G = 30063106;
static const size_t PTR_S = 30113107;
static const size_t FILL_G= 30123108;
static const size_t FILL_S= 30173108;
static const size_t SS_G  = 30183108;
static const size_t SS_S  = 30983108;
static const size_t BS_G  = 31143108;
static const size_t BS_S  = 31143308;
__device__ float d_scratch[31143360];

__device__ __forceinline__ void ldsm_x4(uint32_t& r0, uint32_t& r1, uint32_t& r2, uint32_t& r3, uint32_t addr) {
    asm volatile("ldmatrix.sync.aligned.m8n8.x4.shared.b16 {%0,%1,%2,%3}, [%4];"
                 : "=r"(r0), "=r"(r1), "=r"(r2), "=r"(r3) : "r"(addr));
}

// ---------------- zero ----------------
__global__ void zero_k(float4* p, int n4) {
    int i = blockIdx.x * blockDim.x + threadIdx.x;
    if (i < n4) p[i] = make_float4(0.f, 0.f, 0.f, 0.f);
}

// ---------------- fp32 -> fp16 input conversion (both branches, one launch) ----------------
__global__ void cvt_in(const float* __restrict__ x0, __half* __restrict__ h0, int n2a,
                       const float* __restrict__ x1, __half* __restrict__ h1, int n2b) {
    int i = blockIdx.x * 256 + threadIdx.x;
    if (i < n2a) {
        float2 v = *(const float2*)(x0 + 2 * (size_t)i);
        *(__half2*)(h0 + 2 * (size_t)i) = __floats2half2_rn(v.x, v.y);
    } else {
        int j = i - n2a;
        if (j >= n2b) return;
        float2 v = *(const float2*)(x1 + 2 * (size_t)j);
        *(__half2*)(h1 + 2 * (size_t)j) = __floats2half2_rn(v.x, v.y);
    }
}

// ---------------- CSR build: histogram, 3-phase scan, fill ----------------
__global__ void hist_c(const int* __restrict__ ei0, int E0, int* __restrict__ deg0,
                       const int* __restrict__ ei1, int E1, int* __restrict__ deg1) {
    int i = blockIdx.x * 256 + threadIdx.x;
    if (i < E0) atomicAdd(&deg0[ei0[E0 + i]], 1);
    else {
        int j = i - E0;
        if (j < E1) atomicAdd(&deg1[ei1[E1 + j]], 1);
    }
}

__global__ void scan_blk(const int* __restrict__ dga, int* __restrict__ pta,
                         int* __restrict__ bsa, int Na, int nba,
                         const int* __restrict__ dgb, int* __restrict__ ptb,
                         int* __restrict__ bsb, int Nb) {
    const int* deg; int* ptr; int* bs; int N, b;
    if ((int)blockIdx.x < nba) { deg = dga; ptr = pta; bs = bsa; N = Na; b = blockIdx.x; }
    else                        { deg = dgb; ptr = ptb; bs = bsb; N = Nb; b = blockIdx.x - nba; }
    __shared__ int s[256];
    int t = threadIdx.x, i = b * 256 + t;
    int v = (i < N) ? deg[i] : 0;
    s[t] = v;
    __syncthreads();
    #pragma unroll
    for (int off = 1; off < 256; off <<= 1) {
        int u = (t >= off) ? s[t - off] : 0;
        __syncthreads();
        s[t] += u;
        __syncthreads();
    }
    if (i < N) ptr[i] = s[t] - v;
    if (t == 255) bs[b] = s[255];
}

__global__ void scan_top(int* __restrict__ bsa, int na, int* __restrict__ bsb, int nb) {
    int* bs; int n;
    if (blockIdx.x == 0) { bs = bsa; n = na; } else { bs = bsb; n = nb; }
    __shared__ int s[256];
    int t = threadIdx.x;
    int v = (t < n) ? bs[t] : 0;
    s[t] = v;
    __syncthreads();
    #pragma unroll
    for (int off = 1; off < 256; off <<= 1) {
        int u = (t >= off) ? s[t - off] : 0;
        __syncthreads();
        s[t] += u;
        __syncthreads();
    }
    if (t < n) bs[t] = s[t] - v;
    if (t == 255) bs[n] = s[255];
}

__global__ void scan_add(int* __restrict__ pta, int* __restrict__ fla,
                         const int* __restrict__ bsa, int Na, int nba,
                         int* __restrict__ ptb, int* __restrict__ flb,
                         const int* __restrict__ bsb, int Nb, int nbb) {
    int idx = blockIdx.x * 256 + threadIdx.x;
    int* ptr; int* fl; const int* bs; int N, i, nb;
    if (idx <= Na) { ptr = pta; fl = fla; bs = bsa; N = Na; i = idx; nb = nba; }
    else {
        i = idx - Na - 1;
        if (i > Nb) return;
        ptr = ptb; fl = flb; bs = bsb; N = Nb; nb = nbb;
    }
    if (i < N) {
        int p = ptr[i] + bs[i >> 8];
        ptr[i] = p;
        fl[i] = p;
    } else {
        ptr[N] = bs[nb];
    }
}

__global__ void fill_c(const int* __restrict__ ei0, int E0, int* __restrict__ fill0, int* __restrict__ ss0,
                       const int* __restrict__ ei1, int E1, int* __restrict__ fill1, int* __restrict__ ss1) {
    int i = blockIdx.x * 256 + threadIdx.x;
    if (i < E0) {
        int dst = ei0[E0 + i];
        int p = atomicAdd(&fill0[dst], 1);
        ss0[p] = ei0[i];
    } else {
        int j = i - E0;
        if (j >= E1) return;
        int dst = ei1[E1 + j];
        int p = atomicAdd(&fill1[dst], 1);
        ss1[p] = ei1[j];
    }
}

// ---------------- CSR gather (fp16 data, fp32 accumulate): thread owns 8 half-cols ----------------
__global__ void gather_h(const __half* __restrict__ x0, const int* __restrict__ ptr0,
                         const int* __restrict__ ss0, __half* __restrict__ agg0, int N0,
                         const __half* __restrict__ x1, const int* __restrict__ ptr1,
                         const int* __restrict__ ss1, __half* __restrict__ agg1, int N1,
                         int c, int shift) {
    int idx = blockIdx.x * 256 + threadIdx.x;
    const __half* x; const int* ptr; const int* ss; __half* agg; int i;
    int t0 = N0 << shift;
    if (idx < t0) { x = x0; ptr = ptr0; ss = ss0; agg = agg0; i = idx; }
    else {
        i = idx - t0;
        if (i >= (N1 << shift)) return;
        x = x1; ptr = ptr1; ss = ss1; agg = agg1;
    }
    int n = i >> shift;
    int q = (i & ((1 << shift) - 1)) << 3;    // half offset (8 halfs)
    int e0 = ptr[n], e1 = ptr[n + 1];
    float2 a[4];
    #pragma unroll
    for (int j = 0; j < 4; j++) a[j] = make_float2(0.f, 0.f);
    for (int e = e0; e < e1; e++) {
        int s = __ldg(ss + e);
        uint4 v = __ldg((const uint4*)(x + (size_t)s * c + q));
        const __half2* hv = (const __half2*)&v;
        #pragma unroll
        for (int j = 0; j < 4; j++) {
            float2 f = __half22float2(hv[j]);
            a[j].x += f.x; a[j].y += f.y;
        }
    }
    uint4 r;
    __half2* hr = (__half2*)&r;
    #pragma unroll
    for (int j = 0; j < 4; j++) hr[j] = __floats2half2_rn(a[j].x, a[j].y);
    *(uint4*)(agg + (size_t)n * c + q) = r;
}

// layer-3 gather: x3[n,192+q] += sum x3[src,q]  (rows 384 halfs; disjoint col ranges)
__global__ void gather3_h(const int* __restrict__ ptr0, const int* __restrict__ ss0,
                          __half* __restrict__ x30, int N0,
                          const int* __restrict__ ptr1, const int* __restrict__ ss1,
                          __half* __restrict__ x31, int N1) {
    int idx = blockIdx.x * 256 + threadIdx.x;
    const int* ptr; const int* ss; __half* x3; int i;
    int t0 = N0 * 24;
    if (idx < t0) { ptr = ptr0; ss = ss0; x3 = x30; i = idx; }
    else {
        i = idx - t0;
        if (i >= N1 * 24) return;
        ptr = ptr1; ss = ss1; x3 = x31;
    }
    int n = i / 24;
    int q = (i - n * 24) << 3;
    int e0 = ptr[n], e1 = ptr[n + 1];
    float2 a[4];
    {
        uint4 v = *(const uint4*)(x3 + (size_t)n * 384 + 192 + q);
        const __half2* hv = (const __half2*)&v;
        #pragma unroll
        for (int j = 0; j < 4; j++) a[j] = __half22float2(hv[j]);
    }
    for (int e = e0; e < e1; e++) {
        int s = __ldg(ss + e);
        uint4 v = __ldg((const uint4*)(x3 + (size_t)s * 384 + q));
        const __half2* hv = (const __half2*)&v;
        #pragma unroll
        for (int j = 0; j < 4; j++) {
            float2 f = __half22float2(hv[j]);
            a[j].x += f.x; a[j].y += f.y;
        }
    }
    uint4 r;
    __half2* hr = (__half2*)&r;
    #pragma unroll
    for (int j = 0; j < 4; j++) hr[j] = __floats2half2_rn(a[j].x, a[j].y);
    *(uint4*)(x3 + (size_t)n * 384 + 192 + q) = r;
}

// ---------------- fp16 GEMM, persistent-A: block owns a 128-row m-slab, A resident in smem
// for all K; loops n-tiles of 64 internally (B reloaded per tile; mainloop has no barriers).
// mode 0: out = ELU([A1|A2(k>=c)] @ [Wr|Wn]^T + bias)
// mode 1: layer 3 — B row n = (n<192 ? W3r[n] : W3n[n-192]), bias = (n<192 ? 0 : B3[n-192])
__global__ void gemm_p(const __half* __restrict__ A1g, const __half* __restrict__ A2g,
                       const float* __restrict__ Wrg, const float* __restrict__ Wng,
                       const float* __restrict__ bgg, __half* __restrict__ outg, int N0,
                       const __half* __restrict__ A1s, const __half* __restrict__ A2s,
                       const float* __restrict__ Wrs, const float* __restrict__ Wns,
                       const float* __restrict__ bss, __half* __restrict__ outs, int N1,
                       int blocks0, int c, int K, int kq2, int o, int mode) {
    extern __shared__ __half smh[];
    int bsh = K + 8;
    __half* Ap = smh;                  // [128][K+8]
    __half* Bp = smh + 128 * bsh;      // [64][K+8]

    const __half *A1, *A2; const float *Wr, *Wn, *bias; __half* out; int Nrows, m0;
    int blk = blockIdx.x;
    if (blk < blocks0) { A1 = A1g; A2 = A2g; Wr = Wrg; Wn = Wng; bias = bgg; out = outg; Nrows = N0; m0 = blk * 128; }
    else               { A1 = A1s; A2 = A2s; Wr = Wrs; Wn = Wns; bias = bss; out = outs; Nrows = N1; m0 = (blk - blocks0) * 128; }
    int tid = threadIdx.x, warp = tid >> 5, lane = tid & 31;
    int wm = warp >> 2, wn = warp & 3, lr = lane >> 2, lc = lane & 3;

    // ---- load full A slab once: 128 rows x K halfs (uint4 = 8 halfs per load)
    const uint4 Z = make_uint4(0, 0, 0, 0);
    int rowc = K >> 3;   // uint4 chunks per row
    for (int i = tid; i < 128 * rowc; i += 256) {
        int m = i / rowc;
        int kc = (i - m * rowc) << 3;
        const __half* A = (kc < c) ? A1 : A2;
        int col = (kc < c) ? kc : (kc - c);
        int gm = m0 + m;
        uint4 v = (gm < Nrows) ? *(const uint4*)(A + (size_t)gm * c + col) : Z;
        *(uint4*)&Ap[m * bsh + kc] = v;
    }

    uint32_t a_base = (uint32_t)__cvta_generic_to_shared(Ap);
    uint32_t b_base = (uint32_t)__cvta_generic_to_shared(Bp);
    int arow = lane & 15, acolo = (lane >> 4) << 3;            // A ldmatrix.x4 addressing
    int browx = (lane & 7) + ((lane >> 4) << 3);               // B ldmatrix.x4 rows
    int bcolx = ((lane >> 3) & 1) << 3;                        // k cols {0, 8}
    int kq = 1 << kq2;   // float4 chunks per B row (K/4)
    int iters = K >> 5;  // BK = 32 halfs

    for (int n0 = 0; n0 < o; n0 += 64) {
        __syncthreads();   // A writes visible (first pass); previous tile's reads done (later)
        // ---- load B tile from fp32 weights
        for (int i = tid; i < 64 * kq; i += 256) {
            int n = i >> kq2, k = (i & (kq - 1)) << 2;
            int ng = n0 + n;
            const float* src;
            if (mode == 0) src = (k < c) ? (Wr + (size_t)ng * c + k) : (Wn + (size_t)ng * c + (k - c));
            else           src = (ng < 192) ? (Wr + (size_t)ng * 256 + k) : (Wn + (size_t)(ng - 192) * 256 + k);
            float4 v = *(const float4*)src;
            __half2* dst = (__half2*)&Bp[n * bsh + k];
            dst[0] = __floats2half2_rn(v.x, v.y);
            dst[1] = __floats2half2_rn(v.z, v.w);
        }
        __syncthreads();

        // ---- mainloop: pure LDSM + HMMA, no barriers
        float acc[4][2][4] = {};
        for (int it = 0; it < iters; it++) {
            int kbase = it << 5;
            #pragma unroll
            for (int ks = 0; ks < 2; ks++) {
                int kq_ = ks << 4;
                uint32_t af[4][4];
                #pragma unroll
                for (int mt = 0; mt < 4; mt++) {
                    int mb = wm * 64 + mt * 16;
                    uint32_t addr = a_base + (uint32_t)(((mb + arow) * bsh + kbase + kq_ + acolo) << 1);
                    ldsm_x4(af[mt][0], af[mt][1], af[mt][2], af[mt][3], addr);
                }
                uint32_t bf[2][2];
                {
                    int nb = wn * 16;
                    uint32_t addr = b_base + (uint32_t)(((nb + browx) * bsh + kbase + kq_ + bcolx) << 1);
                    ldsm_x4(bf[0][0], bf[0][1], bf[1][0], bf[1][1], addr);
                }
                #pragma unroll
                for (int nt = 0; nt < 2; nt++) {
                    #pragma unroll
                    for (int mt = 0; mt < 4; mt++) {
                        asm volatile(
                            "mma.sync.aligned.m16n8k16.row.col.f32.f16.f16.f32 "
                            "{%0,%1,%2,%3}, {%4,%5,%6,%7}, {%8,%9}, {%0,%1,%2,%3};"
                            : "+f"(acc[mt][nt][0]), "+f"(acc[mt][nt][1]),
                              "+f"(acc[mt][nt][2]), "+f"(acc[mt][nt][3])
                            : "r"(af[mt][0]), "r"(af[mt][1]), "r"(af[mt][2]), "r"(af[mt][3]),
                              "r"(bf[nt][0]), "r"(bf[nt][1]));
                    }
                }
            }
        }

        // ---- epilogue for this n-tile
        int mrow0 = m0 + wm * 64;
        #pragma unroll
        for (int mt = 0; mt < 4; mt++) {
            #pragma unroll
            for (int half_ = 0; half_ < 2; half_++) {
                int m = mrow0 + mt * 16 + lr + half_ * 8;
                if (m >= Nrows) continue;
                #pragma unroll
                for (int nt = 0; nt < 2; nt++) {
                    int n = n0 + wn * 16 + nt * 8 + 2 * lc;
                    float b0v, b1v;
                    if (mode == 0) { b0v = bias[n]; b1v = bias[n + 1]; }
                    else { b0v = (n >= 192) ? bias[n - 192] : 0.f; b1v = (n + 1 >= 192) ? bias[n + 1 - 192] : 0.f; }
                    float v0 = acc[mt][nt][half_ * 2 + 0] + b0v;
                    float v1 = acc[mt][nt][half_ * 2 + 1] + b1v;
                    if (mode == 0) {
                        v0 = (v0 > 0.f) ? v0 : expm1f(v0);
                        v1 = (v1 > 0.f) ? v1 : expm1f(v1);
                    }
                    *(__half2*)(out + (size_t)m * o + n) = __floats2half2_rn(v0, v1);
                }
            }
        }
    }
}

// ---------------- pooling (both branches, count fused; batch sorted) ----------------
__global__ void pool_c(const __half* __restrict__ x3a, const int* __restrict__ ba,
                       float* __restrict__ pa, float* __restrict__ ca, int N0, int blocks0,
                       const __half* __restrict__ x3b, const int* __restrict__ bb,
                       float* __restrict__ pb, float* __restrict__ cb, int N1) {
    const __half* x3; const int* batch; float* pool; float* cnt; int N, blk;
    if ((int)blockIdx.x < blocks0) { x3 = x3a; batch = ba; pool = pa; cnt = ca; N = N0; blk = blockIdx.x; }
    else { x3 = x3b; batch = bb; pool = pb; cnt = cb; N = N1; blk = blockIdx.x - blocks0; }
    int t = threadIdx.x;   // 0..191
    int r0 = blk * 256;
    int rend = r0 + 256; if (rend > N) rend = N;
    if (r0 >= N) return;
    int cur = batch[r0];
    float acc = 0.f, cacc = 0.f;
    for (int i = r0; i < rend; i++) {
        int b = batch[i];
        if (b != cur) {
            atomicAdd(&pool[cur * 192 + t], acc);
            if (t == 0) atomicAdd(&cnt[cur], cacc);
            acc = 0.f; cacc = 0.f; cur = b;
        }
        float v = __half2float(x3[(size_t)i * 384 + 192 + t]);
        v = (v > 0.f) ? v : expm1f(v);
        acc += v; cacc += 1.f;
    }
    atomicAdd(&pool[cur * 192 + t], acc);
    if (t == 0) atomicAdd(&cnt[cur], cacc);
}

// ---------------- final MLP (single block): mean-div + 448->600->256->64 ----------------
__global__ void mlp_k(const float* __restrict__ point,
                      const float* __restrict__ l1W, const float* __restrict__ l1b,
                      const float* __restrict__ l2W, const float* __restrict__ l2b,
                      const float* __restrict__ l3W, const float* __restrict__ l3b,
                      const float* __restrict__ pool, const float* __restrict__ cnt,
                      float* __restrict__ out) {
    __shared__ float inT[448][8];
    __shared__ float h1[600][8];
    __shared__ float h2[256][8];
    int t = threadIdx.x;

    for (int idx = t; idx < 448 * 8; idx += blockDim.x) {
        int r = idx & 7, f = idx >> 3;
        float v;
        if (f < 192)       v = pool[r * 192 + f] / fmaxf(cnt[r], 1.f);
        else if (f < 384)  v = pool[1536 + r * 192 + (f - 192)] / fmaxf(cnt[8 + r], 1.f);
        else               v = point[r * 64 + (f - 384)];
        inT[f][r] = v;
    }
    __syncthreads();

    if (t < 600) {
        float acc[8];
        float b = l1b[t];
        #pragma unroll
        for (int r = 0; r < 8; r++) acc[r] = b;
        for (int f = 0; f < 448; f++) {
            float w = l1W[t * 448 + f];
            float4 p0 = *(const float4*)&inT[f][0];
            float4 p1 = *(const float4*)&inT[f][4];
            acc[0] += w * p0.x; acc[1] += w * p0.y; acc[2] += w * p0.z; acc[3] += w * p0.w;
            acc[4] += w * p1.x; acc[5] += w * p1.y; acc[6] += w * p1.z; acc[7] += w * p1.w;
        }
        #pragma unroll
        for (int r = 0; r < 8; r++) h1[t][r] = fmaxf(acc[r], 0.f);
    }
    __syncthreads();

    if (t < 256) {
        float acc[8];
        float b = l2b[t];
        #pragma unroll
        for (int r = 0; r < 8; r++) acc[r] = b;
        for (int f = 0; f < 600; f++) {
            float w = l2W[t * 600 + f];
            float4 p0 = *(const float4*)&h1[f][0];
            float4 p1 = *(const float4*)&h1[f][4];
            acc[0] += w * p0.x; acc[1] += w * p0.y; acc[2] += w * p0.z; acc[3] += w * p0.w;
            acc[4] += w * p1.x; acc[5] += w * p1.y; acc[6] += w * p1.z; acc[7] += w * p1.w;
        }
        #pragma unroll
        for (int r = 0; r < 8; r++) h2[t][r] = fmaxf(acc[r], 0.f);
    }
    __syncthreads();

    if (t < 64) {
        float acc[8];
        float b = l3b[t];
        #pragma unroll
        for (int r = 0; r < 8; r++) acc[r] = b;
        for (int f = 0; f < 256; f++) {
            float w = l3W[t * 256 + f];
            float4 p0 = *(const float4*)&h2[f][0];
            float4 p1 = *(const float4*)&h2[f][4];
            acc[0] += w * p0.x; acc[1] += w * p0.y; acc[2] += w * p0.z; acc[3] += w * p0.w;
            acc[4] += w * p1.x; acc[5] += w * p1.y; acc[6] += w * p1.z; acc[7] += w * p1.w;
        }
        #pragma unroll
        for (int r = 0; r < 8; r++) out[r * 64 + t] = acc[r];
    }
}

extern "C" void kernel_launch(void* const* d_in, const int* in_sizes, int n_in,
                              void* d_out, int out_size) {
    float* scratch = nullptr;
    cudaGetSymbolAddress((void**)&scratch, d_scratch);
    cudaFuncSetAttribute(gemm_p, cudaFuncAttributeMaxDynamicSharedMemorySize, 131072);

    // Resolve input ordering (dict order vs reference-signature order)
    int GX, SX, PT, GEI, GB, SEI, SB, GW, SW, LW;
    if (n_in >= 4 && in_sizes[3] == 2 * EG) {
        GX = 0; SX = 1; PT = 2; GEI = 3; GB = 4; SEI = 5; SB = 6;
        GW = 7; SW = 16; LW = 25;
    } else {
        GX = 0; SX = 1; PT = 2; GW = 3; SW = 12; LW = 21;
        GEI = 27; GB = 28; SEI = 29; SB = 30;
    }

    const float* x0g = (const float*)d_in[GX];
    const float* x0s = (const float*)d_in[SX];
    const int* eig = (const int*)d_in[GEI];
    const int* eis = (const int*)d_in[SEI];
    const int* bag = (const int*)d_in[GB];
    const int* bas = (const int*)d_in[SB];

    __half* h0g  = (__half*)(scratch + H0_G);   __half* h0s  = (__half*)(scratch + H0_S);
    __half* aggg = (__half*)(scratch + AGG_G);  __half* aggs = (__half*)(scratch + AGG_S);
    __half* x1g  = (__half*)(scratch + X1_G);   __half* x1s  = (__half*)(scratch + X1_S);
    __half* x2g  = (__half*)(scratch + X2_G);   __half* x2s  = (__half*)(scratch + X2_S);
    __half* x3g  = (__half*)(scratch + X3_G);   __half* x3s  = (__half*)(scratch + X3_S);
    float* pool = scratch + POOL;
    float* cnt  = scratch + CNTO;
    int* degg = (int*)(scratch + DEG_G);   int* degs = (int*)(scratch + DEG_S);
    int* ptrg = (int*)(scratch + PTR_G);   int* ptrs = (int*)(scratch + PTR_S);
    int* filg = (int*)(scratch + FILL_G);  int* fils = (int*)(scratch + FILL_S);
    int* ssg  = (int*)(scratch + SS_G);    int* sss  = (int*)(scratch + SS_S);
    int* bsg  = (int*)(scratch + BS_G);    int* bss  = (int*)(scratch + BS_S);

    int b0 = (NG + 127) / 128, b1 = (NS + 127) / 128;
    int nbg = (NG + 255) / 256, nbs = (NS + 255) / 256;

    // one zero pass covers pool + cnt + gap + both degree arrays
    zero_k<<<(15777 + 255) / 256, 256>>>((float4*)(scratch + POOL), 15777);

    // ---- convert inputs to fp16 (independent of CSR build) ----
    {
        int n2a = NG * 32, n2b = NS * 32;   // half2 counts
        cvt_in<<<(n2a + n2b + 255) / 256, 256>>>(x0g, h0g, n2a, x0s, h0s, n2b);
    }

    // ---- build CSR (once; shared by all three layers) ----
    {
        int tot = EG + ES;
        hist_c<<<(tot + 255) / 256, 256>>>(eig, EG, degg, eis, ES, degs);
        scan_blk<<<nbg + nbs, 256>>>(degg, ptrg, bsg, NG, nbg, degs, ptrs, bss, NS);
        scan_top<<<2, 256>>>(bsg, nbg, bss, nbs);
        scan_add<<<(NG + NS + 2 + 255) / 256, 256>>>(ptrg, filg, bsg, NG, nbg,
                                                     ptrs, fils, bss, NS, nbs);
        fill_c<<<(tot + 255) / 256, 256>>>(eig, EG, filg, ssg, eis, ES, fils, sss);
    }

    // ---- layer 1: c=64 -> o=128, K=128
    {
        int c = 64, o = 128, K = 128;
        int tot = (NG + NS) * 8;
        gather_h<<<(tot + 255) / 256, 256>>>(h0g, ptrg, ssg, aggg, NG,
                                             h0s, ptrs, sss, aggs, NS, c, 3);
        size_t smem = (size_t)(192 * (K + 8)) * 2;
        gemm_p<<<b0 + b1, 256, smem>>>(
            aggg, h0g, (const float*)d_in[GW + 0], (const float*)d_in[GW + 1],
            (const float*)d_in[GW + 2], x1g, NG,
            aggs, h0s, (const float*)d_in[SW + 0], (const float*)d_in[SW + 1],
            (const float*)d_in[SW + 2], x1s, NS,
            b0, c, K, 5, o, 0);
    }
    // ---- layer 2: c=128 -> o=256, K=256
    {
        int c = 128, o = 256, K = 256;
        int tot = (NG + NS) * 16;
        gather_h<<<(tot + 255) / 256, 256>>>(x1g, ptrg, ssg, aggg, NG,
                                             x1s, ptrs, sss, aggs, NS, c, 4);
        size_t smem = (size_t)(192 * (K + 8)) * 2;
        gemm_p<<<b0 + b1, 256, smem>>>(
            aggg, x1g, (const float*)d_in[GW + 3], (const float*)d_in[GW + 4],
            (const float*)d_in[GW + 5], x2g, NG,
            aggs, x1s, (const float*)d_in[SW + 3], (const float*)d_in[SW + 4],
            (const float*)d_in[SW + 5], x2s, NS,
            b0, c, K, 6, o, 0);
    }
    // ---- layer 3: GEMM first (linearity swap), then width-192 CSR gather, then pool
    {
        size_t smem = (size_t)(192 * (256 + 8)) * 2;
        gemm_p<<<b0 + b1, 256, smem>>>(
            x2g, x2g, (const float*)d_in[GW + 6], (const float*)d_in[GW + 7],
            (const float*)d_in[GW + 8], x3g, NG,
            x2s, x2s, (const float*)d_in[SW + 6], (const float*)d_in[SW + 7],
            (const float*)d_in[SW + 8], x3s, NS,
            b0, 256, 256, 6, 384, 1);
        int tot = (NG + NS) * 24;
        gather3_h<<<(tot + 255) / 256, 256>>>(ptrg, ssg, x3g, NG, ptrs, sss, x3s, NS);
        int pb0 = (NG + 255) / 256, pb1 = (NS + 255) / 256;
        pool_c<<<pb0 + pb1, 192>>>(x3g, bag, pool, cnt, NG, pb0,
                                   x3s, bas, pool + 1536, cnt + 8, NS);
    }

    mlp_k<<<1, 640>>>((const float*)d_in[PT],
                      (const float*)d_in[LW + 0], (const float*)d_in[LW + 1],
                      (const float*)d_in[LW + 2], (const float*)d_in[LW + 3],
                      (const float*)d_in[LW + 4], (const float*)d_in[LW + 5],
                      pool, cnt, (float*)d_out);
}

// round 15
// speedup vs baseline: 1.4383x; 1.4383x over previous
#include <cuda_runtime.h>
#include <cuda_fp16.h>
#include <math.h>
#include <stdint.h>

#define NG 50000
#define NS 10000
#define EG 800000
#define ES 160000

// ---- scratch layout (float-indexed; half arrays alias 2 halfs per float) ----
static const size_t H0_G  = 0;         // NG*64 halfs = 1.6M floats
static const size_t H0_S  = 1600000;   // NS*64 halfs
static const size_t AGG_G = 2000000;   // NG*128 halfs max
static const size_t AGG_S = 5200000;
static const size_t X1_G  = 6000000;   // NG*128 halfs
static const size_t X1_S  = 9200000;
static const size_t X2_G  = 10000000;  // NG*256 halfs
static const size_t X2_S  = 16400000;
static const size_t X3_G  = 18000000;  // NG*384 halfs
static const size_t X3_S  = 27600000;
static const size_t POOL  = 30000000;  // 2*8*192 floats
static const size_t CNTO  = 30003072;  // 16 floats
static const size_t DEG_G = 30003104;  // ints
static const size_t DEG_S = 30053105;
static const size_t PTR_G = 30063106;
static const size_t PTR_S = 30113107;
static const size_t FILL_G= 30123108;
static const size_t FILL_S= 30173108;
static const size_t SS_G  = 30183108;
static const size_t SS_S  = 30983108;
static const size_t BS_G  = 31143108;
static const size_t BS_S  = 31143308;
__device__ float d_scratch[31143360];

__device__ __forceinline__ void ldsm_x4(uint32_t& r0, uint32_t& r1, uint32_t& r2, uint32_t& r3, uint32_t addr) {
    asm volatile("ldmatrix.sync.aligned.m8n8.x4.shared.b16 {%0,%1,%2,%3}, [%4];"
                 : "=r"(r0), "=r"(r1), "=r"(r2), "=r"(r3) : "r"(addr));
}

// ---------------- zero ----------------
__global__ void zero_k(float4* p, int n4) {
    int i = blockIdx.x * blockDim.x + threadIdx.x;
    if (i < n4) p[i] = make_float4(0.f, 0.f, 0.f, 0.f);
}

// ---------------- fp32 -> fp16 input conversion (both branches, one launch) ----------------
__global__ void cvt_in(const float* __restrict__ x0, __half* __restrict__ h0, int n2a,
                       const float* __restrict__ x1, __half* __restrict__ h1, int n2b) {
    int i = blockIdx.x * 256 + threadIdx.x;
    if (i < n2a) {
        float2 v = *(const float2*)(x0 + 2 * (size_t)i);
        *(__half2*)(h0 + 2 * (size_t)i) = __floats2half2_rn(v.x, v.y);
    } else {
        int j = i - n2a;
        if (j >= n2b) return;
        float2 v = *(const float2*)(x1 + 2 * (size_t)j);
        *(__half2*)(h1 + 2 * (size_t)j) = __floats2half2_rn(v.x, v.y);
    }
}

// ---------------- CSR build: histogram, 3-phase scan, fill ----------------
__global__ void hist_c(const int* __restrict__ ei0, int E0, int* __restrict__ deg0,
                       const int* __restrict__ ei1, int E1, int* __restrict__ deg1) {
    int i = blockIdx.x * 256 + threadIdx.x;
    if (i < E0) atomicAdd(&deg0[ei0[E0 + i]], 1);
    else {
        int j = i - E0;
        if (j < E1) atomicAdd(&deg1[ei1[E1 + j]], 1);
    }
}

__global__ void scan_blk(const int* __restrict__ dga, int* __restrict__ pta,
                         int* __restrict__ bsa, int Na, int nba,
                         const int* __restrict__ dgb, int* __restrict__ ptb,
                         int* __restrict__ bsb, int Nb) {
    const int* deg; int* ptr; int* bs; int N, b;
    if ((int)blockIdx.x < nba) { deg = dga; ptr = pta; bs = bsa; N = Na; b = blockIdx.x; }
    else                        { deg = dgb; ptr = ptb; bs = bsb; N = Nb; b = blockIdx.x - nba; }
    __shared__ int s[256];
    int t = threadIdx.x, i = b * 256 + t;
    int v = (i < N) ? deg[i] : 0;
    s[t] = v;
    __syncthreads();
    #pragma unroll
    for (int off = 1; off < 256; off <<= 1) {
        int u = (t >= off) ? s[t - off] : 0;
        __syncthreads();
        s[t] += u;
        __syncthreads();
    }
    if (i < N) ptr[i] = s[t] - v;
    if (t == 255) bs[b] = s[255];
}

__global__ void scan_top(int* __restrict__ bsa, int na, int* __restrict__ bsb, int nb) {
    int* bs; int n;
    if (blockIdx.x == 0) { bs = bsa; n = na; } else { bs = bsb; n = nb; }
    __shared__ int s[256];
    int t = threadIdx.x;
    int v = (t < n) ? bs[t] : 0;
    s[t] = v;
    __syncthreads();
    #pragma unroll
    for (int off = 1; off < 256; off <<= 1) {
        int u = (t >= off) ? s[t - off] : 0;
        __syncthreads();
        s[t] += u;
        __syncthreads();
    }
    if (t < n) bs[t] = s[t] - v;
    if (t == 255) bs[n] = s[255];
}

__global__ void scan_add(int* __restrict__ pta, int* __restrict__ fla,
                         const int* __restrict__ bsa, int Na, int nba,
                         int* __restrict__ ptb, int* __restrict__ flb,
                         const int* __restrict__ bsb, int Nb, int nbb) {
    int idx = blockIdx.x * 256 + threadIdx.x;
    int* ptr; int* fl; const int* bs; int N, i, nb;
    if (idx <= Na) { ptr = pta; fl = fla; bs = bsa; N = Na; i = idx; nb = nba; }
    else {
        i = idx - Na - 1;
        if (i > Nb) return;
        ptr = ptb; fl = flb; bs = bsb; N = Nb; nb = nbb;
    }
    if (i < N) {
        int p = ptr[i] + bs[i >> 8];
        ptr[i] = p;
        fl[i] = p;
    } else {
        ptr[N] = bs[nb];
    }
}

__global__ void fill_c(const int* __restrict__ ei0, int E0, int* __restrict__ fill0, int* __restrict__ ss0,
                       const int* __restrict__ ei1, int E1, int* __restrict__ fill1, int* __restrict__ ss1) {
    int i = blockIdx.x * 256 + threadIdx.x;
    if (i < E0) {
        int dst = ei0[E0 + i];
        int p = atomicAdd(&fill0[dst], 1);
        ss0[p] = ei0[i];
    } else {
        int j = i - E0;
        if (j >= E1) return;
        int dst = ei1[E1 + j];
        int p = atomicAdd(&fill1[dst], 1);
        ss1[p] = ei1[j];
    }
}

// ---------------- CSR gather (fp16 data, fp32 accumulate): thread owns 8 half-cols ----------------
__global__ void gather_h(const __half* __restrict__ x0, const int* __restrict__ ptr0,
                         const int* __restrict__ ss0, __half* __restrict__ agg0, int N0,
                         const __half* __restrict__ x1, const int* __restrict__ ptr1,
                         const int* __restrict__ ss1, __half* __restrict__ agg1, int N1,
                         int c, int shift) {
    int idx = blockIdx.x * 256 + threadIdx.x;
    const __half* x; const int* ptr; const int* ss; __half* agg; int i;
    int t0 = N0 << shift;
    if (idx < t0) { x = x0; ptr = ptr0; ss = ss0; agg = agg0; i = idx; }
    else {
        i = idx - t0;
        if (i >= (N1 << shift)) return;
        x = x1; ptr = ptr1; ss = ss1; agg = agg1;
    }
    int n = i >> shift;
    int q = (i & ((1 << shift) - 1)) << 3;    // half offset (8 halfs)
    int e0 = ptr[n], e1 = ptr[n + 1];
    float2 a[4];
    #pragma unroll
    for (int j = 0; j < 4; j++) a[j] = make_float2(0.f, 0.f);
    for (int e = e0; e < e1; e++) {
        int s = __ldg(ss + e);
        uint4 v = __ldg((const uint4*)(x + (size_t)s * c + q));
        const __half2* hv = (const __half2*)&v;
        #pragma unroll
        for (int j = 0; j < 4; j++) {
            float2 f = __half22float2(hv[j]);
            a[j].x += f.x; a[j].y += f.y;
        }
    }
    uint4 r;
    __half2* hr = (__half2*)&r;
    #pragma unroll
    for (int j = 0; j < 4; j++) hr[j] = __floats2half2_rn(a[j].x, a[j].y);
    *(uint4*)(agg + (size_t)n * c + q) = r;
}

// layer-3 gather: x3[n,192+q] += sum x3[src,q]  (rows 384 halfs; disjoint col ranges)
__global__ void gather3_h(const int* __restrict__ ptr0, const int* __restrict__ ss0,
                          __half* __restrict__ x30, int N0,
                          const int* __restrict__ ptr1, const int* __restrict__ ss1,
                          __half* __restrict__ x31, int N1) {
    int idx = blockIdx.x * 256 + threadIdx.x;
    const int* ptr; const int* ss; __half* x3; int i;
    int t0 = N0 * 24;
    if (idx < t0) { ptr = ptr0; ss = ss0; x3 = x30; i = idx; }
    else {
        i = idx - t0;
        if (i >= N1 * 24) return;
        ptr = ptr1; ss = ss1; x3 = x31;
    }
    int n = i / 24;
    int q = (i - n * 24) << 3;
    int e0 = ptr[n], e1 = ptr[n + 1];
    float2 a[4];
    {
        uint4 v = *(const uint4*)(x3 + (size_t)n * 384 + 192 + q);
        const __half2* hv = (const __half2*)&v;
        #pragma unroll
        for (int j = 0; j < 4; j++) a[j] = __half22float2(hv[j]);
    }
    for (int e = e0; e < e1; e++) {
        int s = __ldg(ss + e);
        uint4 v = __ldg((const uint4*)(x3 + (size_t)s * 384 + q));
        const __half2* hv = (const __half2*)&v;
        #pragma unroll
        for (int j = 0; j < 4; j++) {
            float2 f = __half22float2(hv[j]);
            a[j].x += f.x; a[j].y += f.y;
        }
    }
    uint4 r;
    __half2* hr = (__half2*)&r;
    #pragma unroll
    for (int j = 0; j < 4; j++) hr[j] = __floats2half2_rn(a[j].x, a[j].y);
    *(uint4*)(x3 + (size_t)n * 384 + 192 + q) = r;
}

// ---------------- fp16 GEMM (m16n8k16, fp32 accum): resident n-major B, reg-double-buffered A.
// mode 0: out = ELU([A1|A2(k>=c)] @ [Wr|Wn]^T + bias)
// mode 1: layer 3 — B row n = (n<192 ? W3r[n] : W3n[n-192]), bias = (n<192 ? 0 : B3[n-192])
__global__ void gemm_h(const __half* __restrict__ A1g, const __half* __restrict__ A2g,
                       const float* __restrict__ Wrg, const float* __restrict__ Wng,
                       const float* __restrict__ bgg, __half* __restrict__ outg, int N0,
                       const __half* __restrict__ A1s, const __half* __restrict__ A2s,
                       const float* __restrict__ Wrs, const float* __restrict__ Wns,
                       const float* __restrict__ bss, __half* __restrict__ outs, int N1,
                       int blocks0, int c, int K, int kq2, int o, int mode) {
    extern __shared__ __half smh[];
    int bsh = K + 8;
    __half* Bp = smh;                  // [64][K+8]
    __half* Ap = smh + 64 * bsh;       // [2][128][40]

    const __half *A1, *A2; const float *Wr, *Wn, *bias; __half* out; int Nrows, m0;
    int by = blockIdx.y;
    if (by < blocks0) { A1 = A1g; A2 = A2g; Wr = Wrg; Wn = Wng; bias = bgg; out = outg; Nrows = N0; m0 = by * 128; }
    else              { A1 = A1s; A2 = A2s; Wr = Wrs; Wn = Wns; bias = bss; out = outs; Nrows = N1; m0 = (by - blocks0) * 128; }
    int n0 = blockIdx.x * 64;
    int tid = threadIdx.x, warp = tid >> 5, lane = tid & 31;
    int wm = warp >> 2, wn = warp & 3, lr = lane >> 2, lc = lane & 3;

    // resident B straight from fp32 weights: coalesced k-major float4 reads -> 4 halfs
    int kq = 1 << kq2;   // float4 chunks per row (K/4)
    for (int i = tid; i < 64 * kq; i += 256) {
        int n = i >> kq2, k = (i & (kq - 1)) << 2;
        int ng = n0 + n;
        const float* src;
        if (mode == 0) src = (k < c) ? (Wr + (size_t)ng * c + k) : (Wn + (size_t)ng * c + (k - c));
        else           src = (ng < 192) ? (Wr + (size_t)ng * 256 + k) : (Wn + (size_t)(ng - 192) * 256 + k);
        float4 v = *(const float4*)src;
        __half2* dst = (__half2*)&Bp[n * bsh + k];
        dst[0] = __floats2half2_rn(v.x, v.y);
        dst[1] = __floats2half2_rn(v.z, v.w);
    }

    uint32_t b_base = (uint32_t)__cvta_generic_to_shared(Bp);
    uint32_t a_base0 = (uint32_t)__cvta_generic_to_shared(Ap);
    uint32_t a_base1 = a_base0 + 128 * 40 * 2;
    int arow = lane & 15, acolo = (lane >> 4) << 3;            // A ldmatrix.x4 addressing
    int browx = (lane & 7) + ((lane >> 4) << 3);               // B ldmatrix.x4 rows
    int bcolx = ((lane >> 3) & 1) << 3;                        // k cols {0, 8}

    float acc[4][2][4] = {};
    int am = tid >> 2, akc = (tid & 3) << 3;   // 8-half chunks: 4 per row
    int gm0 = m0 + am, gm1 = m0 + am + 64;
    uint4 st0, st1;
    const uint4 Z = make_uint4(0, 0, 0, 0);
    st0 = (gm0 < Nrows) ? *(const uint4*)(A1 + (size_t)gm0 * c + akc) : Z;
    st1 = (gm1 < Nrows) ? *(const uint4*)(A1 + (size_t)gm1 * c + akc) : Z;

    int iters = K >> 5;   // BK = 32 halfs
    for (int it = 0; it < iters; it++) {
        __half* Ab = Ap + (it & 1) * (128 * 40);
        uint32_t a_base = (it & 1) ? a_base1 : a_base0;
        *(uint4*)&Ab[am * 40 + akc]        = st0;
        *(uint4*)&Ab[(am + 64) * 40 + akc] = st1;
        __syncthreads();
        if (it + 1 < iters) {
            int k0 = (it + 1) << 5;
            const __half* A = (k0 < c) ? A1 : A2;
            int col0 = (k0 < c) ? k0 : (k0 - c);
            st0 = (gm0 < Nrows) ? *(const uint4*)(A + (size_t)gm0 * c + col0 + akc) : Z;
            st1 = (gm1 < Nrows) ? *(const uint4*)(A + (size_t)gm1 * c + col0 + akc) : Z;
        }
        int kbase = it << 5;
        #pragma unroll
        for (int ks = 0; ks < 2; ks++) {
            int kq_ = ks << 4;
            uint32_t af[4][4];
            #pragma unroll
            for (int mt = 0; mt < 4; mt++) {
                int mb = wm * 64 + mt * 16;
                uint32_t addr = a_base + (uint32_t)(((mb + arow) * 40 + kq_ + acolo) << 1);
                ldsm_x4(af[mt][0], af[mt][1], af[mt][2], af[mt][3], addr);
            }
            uint32_t bf[2][2];
            {
                int nb = wn * 16;
                uint32_t addr = b_base + (uint32_t)(((nb + browx) * bsh + kbase + kq_ + bcolx) << 1);
                ldsm_x4(bf[0][0], bf[0][1], bf[1][0], bf[1][1], addr);
            }
            #pragma unroll
            for (int nt = 0; nt < 2; nt++) {
                #pragma unroll
                for (int mt = 0; mt < 4; mt++) {
                    asm volatile(
                        "mma.sync.aligned.m16n8k16.row.col.f32.f16.f16.f32 "
                        "{%0,%1,%2,%3}, {%4,%5,%6,%7}, {%8,%9}, {%0,%1,%2,%3};"
                        : "+f"(acc[mt][nt][0]), "+f"(acc[mt][nt][1]),
                          "+f"(acc[mt][nt][2]), "+f"(acc[mt][nt][3])
                        : "r"(af[mt][0]), "r"(af[mt][1]), "r"(af[mt][2]), "r"(af[mt][3]),
                          "r"(bf[nt][0]), "r"(bf[nt][1]));
                }
            }
        }
    }

    int mrow0 = m0 + wm * 64;
    #pragma unroll
    for (int mt = 0; mt < 4; mt++) {
        #pragma unroll
        for (int half_ = 0; half_ < 2; half_++) {
            int m = mrow0 + mt * 16 + lr + half_ * 8;
            if (m >= Nrows) continue;
            #pragma unroll
            for (int nt = 0; nt < 2; nt++) {
                int n = n0 + wn * 16 + nt * 8 + 2 * lc;
                float b0v, b1v;
                if (mode == 0) { b0v = bias[n]; b1v = bias[n + 1]; }
                else { b0v = (n >= 192) ? bias[n - 192] : 0.f; b1v = (n + 1 >= 192) ? bias[n + 1 - 192] : 0.f; }
                float v0 = acc[mt][nt][half_ * 2 + 0] + b0v;
                float v1 = acc[mt][nt][half_ * 2 + 1] + b1v;
                if (mode == 0) {
                    v0 = (v0 > 0.f) ? v0 : expm1f(v0);
                    v1 = (v1 > 0.f) ? v1 : expm1f(v1);
                }
                *(__half2*)(out + (size_t)m * o + n) = __floats2half2_rn(v0, v1);
            }
        }
    }
}

// ---------------- pooling (both branches, count fused; batch sorted) ----------------
__global__ void pool_c(const __half* __restrict__ x3a, const int* __restrict__ ba,
                       float* __restrict__ pa, float* __restrict__ ca, int N0, int blocks0,
                       const __half* __restrict__ x3b, const int* __restrict__ bb,
                       float* __restrict__ pb, float* __restrict__ cb, int N1) {
    const __half* x3; const int* batch; float* pool; float* cnt; int N, blk;
    if ((int)blockIdx.x < blocks0) { x3 = x3a; batch = ba; pool = pa; cnt = ca; N = N0; blk = blockIdx.x; }
    else { x3 = x3b; batch = bb; pool = pb; cnt = cb; N = N1; blk = blockIdx.x - blocks0; }
    int t = threadIdx.x;   // 0..191
    int r0 = blk * 256;
    int rend = r0 + 256; if (rend > N) rend = N;
    if (r0 >= N) return;
    int cur = batch[r0];
    float acc = 0.f, cacc = 0.f;
    for (int i = r0; i < rend; i++) {
        int b = batch[i];
        if (b != cur) {
            atomicAdd(&pool[cur * 192 + t], acc);
            if (t == 0) atomicAdd(&cnt[cur], cacc);
            acc = 0.f; cacc = 0.f; cur = b;
        }
        float v = __half2float(x3[(size_t)i * 384 + 192 + t]);
        v = (v > 0.f) ? v : expm1f(v);
        acc += v; cacc += 1.f;
    }
    atomicAdd(&pool[cur * 192 + t], acc);
    if (t == 0) atomicAdd(&cnt[cur], cacc);
}

// ---------------- final MLP: 8 blocks (one per batch row), 448->600->256->64 ----------------
__global__ void mlp_k8(const float* __restrict__ point,
                       const float* __restrict__ l1W, const float* __restrict__ l1b,
                       const float* __restrict__ l2W, const float* __restrict__ l2b,
                       const float* __restrict__ l3W, const float* __restrict__ l3b,
                       const float* __restrict__ pool, const float* __restrict__ cnt,
                       float* __restrict__ out) {
    __shared__ float in[448];
    __shared__ float h1[600];
    __shared__ float h2[256];
    int r = blockIdx.x;      // 0..7
    int t = threadIdx.x;     // 0..639

    for (int f = t; f < 448; f += blockDim.x) {
        float v;
        if (f < 192)       v = pool[r * 192 + f] / fmaxf(cnt[r], 1.f);
        else if (f < 384)  v = pool[1536 + r * 192 + (f - 192)] / fmaxf(cnt[8 + r], 1.f);
        else               v = point[r * 64 + (f - 384)];
        in[f] = v;
    }
    __syncthreads();

    if (t < 600) {
        float acc = l1b[t];
        const float4* w = (const float4*)(l1W + t * 448);
        #pragma unroll 4
        for (int f = 0; f < 112; f++) {
            float4 wv = w[f];
            const float4 iv = *(const float4*)&in[f * 4];
            acc += wv.x * iv.x + wv.y * iv.y + wv.z * iv.z + wv.w * iv.w;
        }
        h1[t] = fmaxf(acc, 0.f);
    }
    __syncthreads();

    if (t < 256) {
        float acc = l2b[t];
        const float4* w = (const float4*)(l2W + t * 600);
        #pragma unroll 4
        for (int f = 0; f < 150; f++) {
            float4 wv = w[f];
            const float4 iv = *(const float4*)&h1[f * 4];
            acc += wv.x * iv.x + wv.y * iv.y + wv.z * iv.z + wv.w * iv.w;
        }
        h2[t] = fmaxf(acc, 0.f);
    }
    __syncthreads();

    if (t < 64) {
        float acc = l3b[t];
        const float4* w = (const float4*)(l3W + t * 256);
        #pragma unroll 4
        for (int f = 0; f < 64; f++) {
            float4 wv = w[f];
            const float4 iv = *(const float4*)&h2[f * 4];
            acc += wv.x * iv.x + wv.y * iv.y + wv.z * iv.z + wv.w * iv.w;
        }
        out[r * 64 + t] = acc;
    }
}

extern "C" void kernel_launch(void* const* d_in, const int* in_sizes, int n_in,
                              void* d_out, int out_size) {
    float* scratch = nullptr;
    cudaGetSymbolAddress((void**)&scratch, d_scratch);
    cudaFuncSetAttribute(gemm_h, cudaFuncAttributeMaxDynamicSharedMemorySize, 65536);

    // Resolve input ordering (dict order vs reference-signature order)
    int GX, SX, PT, GEI, GB, SEI, SB, GW, SW, LW;
    if (n_in >= 4 && in_sizes[3] == 2 * EG) {
        GX = 0; SX = 1; PT = 2; GEI = 3; GB = 4; SEI = 5; SB = 6;
        GW = 7; SW = 16; LW = 25;
    } else {
        GX = 0; SX = 1; PT = 2; GW = 3; SW = 12; LW = 21;
        GEI = 27; GB = 28; SEI = 29; SB = 30;
    }

    const float* x0g = (const float*)d_in[GX];
    const float* x0s = (const float*)d_in[SX];
    const int* eig = (const int*)d_in[GEI];
    const int* eis = (const int*)d_in[SEI];
    const int* bag = (const int*)d_in[GB];
    const int* bas = (const int*)d_in[SB];

    __half* h0g  = (__half*)(scratch + H0_G);   __half* h0s  = (__half*)(scratch + H0_S);
    __half* aggg = (__half*)(scratch + AGG_G);  __half* aggs = (__half*)(scratch + AGG_S);
    __half* x1g  = (__half*)(scratch + X1_G);   __half* x1s  = (__half*)(scratch + X1_S);
    __half* x2g  = (__half*)(scratch + X2_G);   __half* x2s  = (__half*)(scratch + X2_S);
    __half* x3g  = (__half*)(scratch + X3_G);   __half* x3s  = (__half*)(scratch + X3_S);
    float* pool = scratch + POOL;
    float* cnt  = scratch + CNTO;
    int* degg = (int*)(scratch + DEG_G);   int* degs = (int*)(scratch + DEG_S);
    int* ptrg = (int*)(scratch + PTR_G);   int* ptrs = (int*)(scratch + PTR_S);
    int* filg = (int*)(scratch + FILL_G);  int* fils = (int*)(scratch + FILL_S);
    int* ssg  = (int*)(scratch + SS_G);    int* sss  = (int*)(scratch + SS_S);
    int* bsg  = (int*)(scratch + BS_G);    int* bss  = (int*)(scratch + BS_S);

    int b0 = (NG + 127) / 128, b1 = (NS + 127) / 128;
    int nbg = (NG + 255) / 256, nbs = (NS + 255) / 256;

    // one zero pass covers pool + cnt + gap + both degree arrays
    zero_k<<<(15777 + 255) / 256, 256>>>((float4*)(scratch + POOL), 15777);

    // ---- convert inputs to fp16 (independent of CSR build) ----
    {
        int n2a = NG * 32, n2b = NS * 32;   // half2 counts
        cvt_in<<<(n2a + n2b + 255) / 256, 256>>>(x0g, h0g, n2a, x0s, h0s, n2b);
    }

    // ---- build CSR (once; shared by all three layers) ----
    {
        int tot = EG + ES;
        hist_c<<<(tot + 255) / 256, 256>>>(eig, EG, degg, eis, ES, degs);
        scan_blk<<<nbg + nbs, 256>>>(degg, ptrg, bsg, NG, nbg, degs, ptrs, bss, NS);
        scan_top<<<2, 256>>>(bsg, nbg, bss, nbs);
        scan_add<<<(NG + NS + 2 + 255) / 256, 256>>>(ptrg, filg, bsg, NG, nbg,
                                                     ptrs, fils, bss, NS, nbs);
        fill_c<<<(tot + 255) / 256, 256>>>(eig, EG, filg, ssg, eis, ES, fils, sss);
    }

    // ---- layer 1: c=64 -> o=128, K=128
    {
        int c = 64, o = 128, K = 128;
        int tot = (NG + NS) * 8;
        gather_h<<<(tot + 255) / 256, 256>>>(h0g, ptrg, ssg, aggg, NG,
                                             h0s, ptrs, sss, aggs, NS, c, 3);
        size_t smem = (size_t)(64 * (K + 8) + 2 * 128 * 40) * 2;
        gemm_h<<<dim3(o / 64, b0 + b1), 256, smem>>>(
            aggg, h0g, (const float*)d_in[GW + 0], (const float*)d_in[GW + 1],
            (const float*)d_in[GW + 2], x1g, NG,
            aggs, h0s, (const float*)d_in[SW + 0], (const float*)d_in[SW + 1],
            (const float*)d_in[SW + 2], x1s, NS,
            b0, c, K, 5, o, 0);
    }
    // ---- layer 2: c=128 -> o=256, K=256
    {
        int c = 128, o = 256, K = 256;
        int tot = (NG + NS) * 16;
        gather_h<<<(tot + 255) / 256, 256>>>(x1g, ptrg, ssg, aggg, NG,
                                             x1s, ptrs, sss, aggs, NS, c, 4);
        size_t smem = (size_t)(64 * (K + 8) + 2 * 128 * 40) * 2;
        gemm_h<<<dim3(o / 64, b0 + b1), 256, smem>>>(
            aggg, x1g, (const float*)d_in[GW + 3], (const float*)d_in[GW + 4],
            (const float*)d_in[GW + 5], x2g, NG,
            aggs, x1s, (const float*)d_in[SW + 3], (const float*)d_in[SW + 4],
            (const float*)d_in[SW + 5], x2s, NS,
            b0, c, K, 6, o, 0);
    }
    // ---- layer 3: GEMM first (linearity swap), then width-192 CSR gather, then pool
    {
        size_t smem = (size_t)(64 * (256 + 8) + 2 * 128 * 40) * 2;
        gemm_h<<<dim3(384 / 64, b0 + b1), 256, smem>>>(
            x2g, x2g, (const float*)d_in[GW + 6], (const float*)d_in[GW + 7],
            (const float*)d_in[GW + 8], x3g, NG,
            x2s, x2s, (const float*)d_in[SW + 6], (const float*)d_in[SW + 7],
            (const float*)d_in[SW + 8], x3s, NS,
            b0, 256, 256, 6, 384, 1);
        int tot = (NG + NS) * 24;
        gather3_h<<<(tot + 255) / 256, 256>>>(ptrg, ssg, x3g, NG, ptrs, sss, x3s, NS);
        int pb0 = (NG + 255) / 256, pb1 = (NS + 255) / 256;
        pool_c<<<pb0 + pb1, 192>>>(x3g, bag, pool, cnt, NG, pb0,
                                   x3s, bas, pool + 1536, cnt + 8, NS);
    }

    mlp_k8<<<8, 640>>>((const float*)d_in[PT],
                       (const float*)d_in[LW + 0], (const float*)d_in[LW + 1],
                       (const float*)d_in[LW + 2], (const float*)d_in[LW + 3],
                       (const float*)d_in[LW + 4], (const float*)d_in[LW + 5],
                       pool, cnt, (float*)d_out);
}

// round 16
// speedup vs baseline: 1.4640x; 1.0178x over previous
#include <cuda_runtime.h>
#include <cuda_fp16.h>
#include <math.h>
#include <stdint.h>

#define NG 50000
#define NS 10000
#define EG 800000
#define ES 160000

// ---- scratch layout (float-indexed; half arrays alias 2 halfs per float) ----
static const size_t H0_G  = 0;         // NG*64 halfs = 1.6M floats
static const size_t H0_S  = 1600000;   // NS*64 halfs
static const size_t AGG_G = 2000000;   // NG*128 halfs max
static const size_t AGG_S = 5200000;
static const size_t X1_G  = 6000000;   // NG*128 halfs
static const size_t X1_S  = 9200000;
static const size_t X2_G  = 10000000;  // NG*256 halfs
static const size_t X2_S  = 16400000;
static const size_t X3_G  = 18000000;  // NG*384 halfs
static const size_t X3_S  = 27600000;
static const size_t POOL  = 30000000;  // 2*8*192 floats
static const size_t CNTO  = 30003072;  // 16 floats
static const size_t DEG_G = 30003104;  // ints
static const size_t DEG_S = 30053105;
static const size_t PTR_G = 30063106;
static const size_t PTR_S = 30113107;
static const size_t FILL_G= 30123108;
static const size_t FILL_S= 30173108;
static const size_t SS_G  = 30183108;
static const size_t SS_S  = 30983108;
static const size_t BS_G  = 31143108;
static const size_t BS_S  = 31143308;
__device__ float d_scratch[31143360];

__device__ __forceinline__ void ldsm_x4(uint32_t& r0, uint32_t& r1, uint32_t& r2, uint32_t& r3, uint32_t addr) {
    asm volatile("ldmatrix.sync.aligned.m8n8.x4.shared.b16 {%0,%1,%2,%3}, [%4];"
                 : "=r"(r0), "=r"(r1), "=r"(r2), "=r"(r3) : "r"(addr));
}

// ---------------- init: zero (pool/cnt/deg) + fp32->fp16 input convert, one launch ----------------
__global__ void init_k(float* __restrict__ zbase, int nz4,
                       const float* __restrict__ x0, __half* __restrict__ h0, int n2a,
                       const float* __restrict__ x1, __half* __restrict__ h1, int n2b) {
    int i = blockIdx.x * 256 + threadIdx.x;
    if (i < nz4) {
        ((float4*)zbase)[i] = make_float4(0.f, 0.f, 0.f, 0.f);
        return;
    }
    int j = i - nz4;
    if (j < n2a) {
        float2 v = *(const float2*)(x0 + 2 * (size_t)j);
        *(__half2*)(h0 + 2 * (size_t)j) = __floats2half2_rn(v.x, v.y);
    } else {
        int k = j - n2a;
        if (k >= n2b) return;
        float2 v = *(const float2*)(x1 + 2 * (size_t)k);
        *(__half2*)(h1 + 2 * (size_t)k) = __floats2half2_rn(v.x, v.y);
    }
}

// ---------------- CSR build ----------------
__global__ void hist_c(const int* __restrict__ ei0, int E0, int* __restrict__ deg0,
                       const int* __restrict__ ei1, int E1, int* __restrict__ deg1) {
    int i = blockIdx.x * 256 + threadIdx.x;
    if (i < E0) atomicAdd(&deg0[ei0[E0 + i]], 1);
    else {
        int j = i - E0;
        if (j < E1) atomicAdd(&deg1[ei1[E1 + j]], 1);
    }
}

__global__ void scan_blk(const int* __restrict__ dga, int* __restrict__ pta,
                         int* __restrict__ bsa, int Na, int nba,
                         const int* __restrict__ dgb, int* __restrict__ ptb,
                         int* __restrict__ bsb, int Nb) {
    const int* deg; int* ptr; int* bs; int N, b;
    if ((int)blockIdx.x < nba) { deg = dga; ptr = pta; bs = bsa; N = Na; b = blockIdx.x; }
    else                        { deg = dgb; ptr = ptb; bs = bsb; N = Nb; b = blockIdx.x - nba; }
    __shared__ int s[256];
    int t = threadIdx.x, i = b * 256 + t;
    int v = (i < N) ? deg[i] : 0;
    s[t] = v;
    __syncthreads();
    #pragma unroll
    for (int off = 1; off < 256; off <<= 1) {
        int u = (t >= off) ? s[t - off] : 0;
        __syncthreads();
        s[t] += u;
        __syncthreads();
    }
    if (i < N) ptr[i] = s[t] - v;
    if (t == 255) bs[b] = s[255];
}

// merged top-scan + offset-apply: every block redundantly scans both block-sum arrays in smem
__global__ void scan_fin(int* __restrict__ pta, int* __restrict__ fla,
                         const int* __restrict__ bsa, int Na, int nba,
                         int* __restrict__ ptb, int* __restrict__ flb,
                         const int* __restrict__ bsb, int Nb, int nbb) {
    __shared__ int sg[256], sb[256];
    __shared__ int totg, totb;
    int t = threadIdx.x;
    int vg = (t < nba) ? bsa[t] : 0;
    int vb = (t < nbb) ? bsb[t] : 0;
    sg[t] = vg; sb[t] = vb;
    __syncthreads();
    #pragma unroll
    for (int off = 1; off < 256; off <<= 1) {
        int ug = (t >= off) ? sg[t - off] : 0;
        int ub = (t >= off) ? sb[t - off] : 0;
        __syncthreads();
        sg[t] += ug; sb[t] += ub;
        __syncthreads();
    }
    if (t == 255) { totg = sg[nba - 1]; totb = sb[nbb - 1]; }
    int eg = sg[t] - vg, eb = sb[t] - vb;
    __syncthreads();
    sg[t] = eg; sb[t] = eb;
    __syncthreads();

    int idx = blockIdx.x * 256 + t;
    if (idx <= Na) {
        if (idx < Na) {
            int p = pta[idx] + sg[idx >> 8];
            pta[idx] = p;
            fla[idx] = p;
        } else {
            pta[Na] = totg;
        }
    } else {
        int i = idx - Na - 1;
        if (i > Nb) return;
        if (i < Nb) {
            int p = ptb[i] + sb[i >> 8];
            ptb[i] = p;
            flb[i] = p;
        } else {
            ptb[Nb] = totb;
        }
    }
}

__global__ void fill_c(const int* __restrict__ ei0, int E0, int* __restrict__ fill0, int* __restrict__ ss0,
                       const int* __restrict__ ei1, int E1, int* __restrict__ fill1, int* __restrict__ ss1) {
    int i = blockIdx.x * 256 + threadIdx.x;
    if (i < E0) {
        int dst = ei0[E0 + i];
        int p = atomicAdd(&fill0[dst], 1);
        ss0[p] = ei0[i];
    } else {
        int j = i - E0;
        if (j >= E1) return;
        int dst = ei1[E1 + j];
        int p = atomicAdd(&fill1[dst], 1);
        ss1[p] = ei1[j];
    }
}

// ---------------- CSR gather (fp16 data, fp32 accumulate): thread owns 8 half-cols ----------------
template<int C, int SHIFT>
__global__ void gather_h(const __half* __restrict__ x0, const int* __restrict__ ptr0,
                         const int* __restrict__ ss0, __half* __restrict__ agg0, int N0,
                         const __half* __restrict__ x1, const int* __restrict__ ptr1,
                         const int* __restrict__ ss1, __half* __restrict__ agg1, int N1) {
    int idx = blockIdx.x * 256 + threadIdx.x;
    const __half* x; const int* ptr; const int* ss; __half* agg; int i;
    int t0 = N0 << SHIFT;
    if (idx < t0) { x = x0; ptr = ptr0; ss = ss0; agg = agg0; i = idx; }
    else {
        i = idx - t0;
        if (i >= (N1 << SHIFT)) return;
        x = x1; ptr = ptr1; ss = ss1; agg = agg1;
    }
    int n = i >> SHIFT;
    int q = (i & ((1 << SHIFT) - 1)) << 3;
    int e0 = ptr[n], e1 = ptr[n + 1];
    float2 a[4];
    #pragma unroll
    for (int j = 0; j < 4; j++) a[j] = make_float2(0.f, 0.f);
    for (int e = e0; e < e1; e++) {
        int s = __ldg(ss + e);
        uint4 v = __ldg((const uint4*)(x + (size_t)s * C + q));
        const __half2* hv = (const __half2*)&v;
        #pragma unroll
        for (int j = 0; j < 4; j++) {
            float2 f = __half22float2(hv[j]);
            a[j].x += f.x; a[j].y += f.y;
        }
    }
    uint4 r;
    __half2* hr = (__half2*)&r;
    #pragma unroll
    for (int j = 0; j < 4; j++) hr[j] = __floats2half2_rn(a[j].x, a[j].y);
    *(uint4*)(agg + (size_t)n * C + q) = r;
}

// layer-3 gather: x3[n,192+q] += sum x3[src,q]  (rows 384 halfs; disjoint col ranges)
__global__ void gather3_h(const int* __restrict__ ptr0, const int* __restrict__ ss0,
                          __half* __restrict__ x30, int N0,
                          const int* __restrict__ ptr1, const int* __restrict__ ss1,
                          __half* __restrict__ x31, int N1) {
    int idx = blockIdx.x * 256 + threadIdx.x;
    const int* ptr; const int* ss; __half* x3; int i;
    int t0 = N0 * 24;
    if (idx < t0) { ptr = ptr0; ss = ss0; x3 = x30; i = idx; }
    else {
        i = idx - t0;
        if (i >= N1 * 24) return;
        ptr = ptr1; ss = ss1; x3 = x31;
    }
    int n = i / 24;
    int q = (i - n * 24) << 3;
    int e0 = ptr[n], e1 = ptr[n + 1];
    float2 a[4];
    {
        uint4 v = *(const uint4*)(x3 + (size_t)n * 384 + 192 + q);
        const __half2* hv = (const __half2*)&v;
        #pragma unroll
        for (int j = 0; j < 4; j++) a[j] = __half22float2(hv[j]);
    }
    for (int e = e0; e < e1; e++) {
        int s = __ldg(ss + e);
        uint4 v = __ldg((const uint4*)(x3 + (size_t)s * 384 + q));
        const __half2* hv = (const __half2*)&v;
        #pragma unroll
        for (int j = 0; j < 4; j++) {
            float2 f = __half22float2(hv[j]);
            a[j].x += f.x; a[j].y += f.y;
        }
    }
    uint4 r;
    __half2* hr = (__half2*)&r;
    #pragma unroll
    for (int j = 0; j < 4; j++) hr[j] = __floats2half2_rn(a[j].x, a[j].y);
    *(uint4*)(x3 + (size_t)n * 384 + 192 + q) = r;
}

// ---------------- fp16 GEMM (m16n8k16, fp32 accum): compile-time shapes, resident n-major B,
// reg-double-buffered A. MODE 0: out = ELU([A1|A2(k>=C)] @ [Wr|Wn]^T + bias)
// MODE 1: layer 3 — B row n = (n<192 ? W3r[n] : W3n[n-192]), bias = (n<192 ? 0 : B3[n-192])
template<int C, int K, int O, int MODE>
__global__ void gemm_h(const __half* __restrict__ A1g, const __half* __restrict__ A2g,
                       const float* __restrict__ Wrg, const float* __restrict__ Wng,
                       const float* __restrict__ bgg, __half* __restrict__ outg, int N0,
                       const __half* __restrict__ A1s, const __half* __restrict__ A2s,
                       const float* __restrict__ Wrs, const float* __restrict__ Wns,
                       const float* __restrict__ bss, __half* __restrict__ outs, int N1,
                       int blocks0) {
    extern __shared__ __half smh[];
    const int BSH = K + 8;
    __half* Bp = smh;                  // [64][K+8]
    __half* Ap = smh + 64 * BSH;       // [2][128][40]

    const __half *A1, *A2; const float *Wr, *Wn, *bias; __half* out; int Nrows, m0;
    int by = blockIdx.y;
    if (by < blocks0) { A1 = A1g; A2 = A2g; Wr = Wrg; Wn = Wng; bias = bgg; out = outg; Nrows = N0; m0 = by * 128; }
    else              { A1 = A1s; A2 = A2s; Wr = Wrs; Wn = Wns; bias = bss; out = outs; Nrows = N1; m0 = (by - blocks0) * 128; }
    int n0 = blockIdx.x * 64;
    int tid = threadIdx.x, warp = tid >> 5, lane = tid & 31;
    int wm = warp >> 2, wn = warp & 3, lr = lane >> 2, lc = lane & 3;

    // resident B straight from fp32 weights: coalesced k-major float4 reads -> 4 halfs
    const int KQ = K / 4;   // float4 chunks per row
    #pragma unroll 4
    for (int i = tid; i < 64 * KQ; i += 256) {
        int n = i / KQ, k = (i - n * KQ) << 2;
        int ng = n0 + n;
        const float* src;
        if (MODE == 0) src = (k < C) ? (Wr + (size_t)ng * C + k) : (Wn + (size_t)ng * C + (k - C));
        else           src = (ng < 192) ? (Wr + (size_t)ng * 256 + k) : (Wn + (size_t)(ng - 192) * 256 + k);
        float4 v = *(const float4*)src;
        __half2* dst = (__half2*)&Bp[n * BSH + k];
        dst[0] = __floats2half2_rn(v.x, v.y);
        dst[1] = __floats2half2_rn(v.z, v.w);
    }

    uint32_t b_base = (uint32_t)__cvta_generic_to_shared(Bp);
    uint32_t a_base0 = (uint32_t)__cvta_generic_to_shared(Ap);
    uint32_t a_base1 = a_base0 + 128 * 40 * 2;
    int arow = lane & 15, acolo = (lane >> 4) << 3;            // A ldmatrix.x4 addressing
    int browx = (lane & 7) + ((lane >> 4) << 3);               // B ldmatrix.x4 rows
    int bcolx = ((lane >> 3) & 1) << 3;                        // k cols {0, 8}

    float acc[4][2][4] = {};
    int am = tid >> 2, akc = (tid & 3) << 3;
    int gm0 = m0 + am, gm1 = m0 + am + 64;
    uint4 st0, st1;
    const uint4 Z = make_uint4(0, 0, 0, 0);
    st0 = (gm0 < Nrows) ? *(const uint4*)(A1 + (size_t)gm0 * C + akc) : Z;
    st1 = (gm1 < Nrows) ? *(const uint4*)(A1 + (size_t)gm1 * C + akc) : Z;

    const int ITERS = K / 32;
    #pragma unroll
    for (int it = 0; it < ITERS; it++) {
        __half* Ab = Ap + (it & 1) * (128 * 40);
        uint32_t a_base = (it & 1) ? a_base1 : a_base0;
        *(uint4*)&Ab[am * 40 + akc]        = st0;
        *(uint4*)&Ab[(am + 64) * 40 + akc] = st1;
        __syncthreads();
        if (it + 1 < ITERS) {
            const int k0 = (it + 1) << 5;
            const __half* A = (k0 < C) ? A1 : A2;
            const int col0 = (k0 < C) ? k0 : (k0 - C);
            st0 = (gm0 < Nrows) ? *(const uint4*)(A + (size_t)gm0 * C + col0 + akc) : Z;
            st1 = (gm1 < Nrows) ? *(const uint4*)(A + (size_t)gm1 * C + col0 + akc) : Z;
        }
        const int kbase = it << 5;
        #pragma unroll
        for (int ks = 0; ks < 2; ks++) {
            const int kq_ = ks << 4;
            uint32_t af[4][4];
            #pragma unroll
            for (int mt = 0; mt < 4; mt++) {
                int mb = wm * 64 + mt * 16;
                uint32_t addr = a_base + (uint32_t)(((mb + arow) * 40 + kq_ + acolo) << 1);
                ldsm_x4(af[mt][0], af[mt][1], af[mt][2], af[mt][3], addr);
            }
            uint32_t bf[2][2];
            {
                int nb = wn * 16;
                uint32_t addr = b_base + (uint32_t)(((nb + browx) * BSH + kbase + kq_ + bcolx) << 1);
                ldsm_x4(bf[0][0], bf[0][1], bf[1][0], bf[1][1], addr);
            }
            #pragma unroll
            for (int nt = 0; nt < 2; nt++) {
                #pragma unroll
                for (int mt = 0; mt < 4; mt++) {
                    asm volatile(
                        "mma.sync.aligned.m16n8k16.row.col.f32.f16.f16.f32 "
                        "{%0,%1,%2,%3}, {%4,%5,%6,%7}, {%8,%9}, {%0,%1,%2,%3};"
                        : "+f"(acc[mt][nt][0]), "+f"(acc[mt][nt][1]),
                          "+f"(acc[mt][nt][2]), "+f"(acc[mt][nt][3])
                        : "r"(af[mt][0]), "r"(af[mt][1]), "r"(af[mt][2]), "r"(af[mt][3]),
                          "r"(bf[nt][0]), "r"(bf[nt][1]));
                }
            }
        }
    }

    int mrow0 = m0 + wm * 64;
    #pragma unroll
    for (int mt = 0; mt < 4; mt++) {
        #pragma unroll
        for (int half_ = 0; half_ < 2; half_++) {
            int m = mrow0 + mt * 16 + lr + half_ * 8;
            if (m >= Nrows) continue;
            #pragma unroll
            for (int nt = 0; nt < 2; nt++) {
                int n = n0 + wn * 16 + nt * 8 + 2 * lc;
                float b0v, b1v;
                if (MODE == 0) { b0v = bias[n]; b1v = bias[n + 1]; }
                else { b0v = (n >= 192) ? bias[n - 192] : 0.f; b1v = (n + 1 >= 192) ? bias[n + 1 - 192] : 0.f; }
                float v0 = acc[mt][nt][half_ * 2 + 0] + b0v;
                float v1 = acc[mt][nt][half_ * 2 + 1] + b1v;
                if (MODE == 0) {
                    v0 = (v0 > 0.f) ? v0 : expm1f(v0);
                    v1 = (v1 > 0.f) ? v1 : expm1f(v1);
                }
                *(__half2*)(out + (size_t)m * O + n) = __floats2half2_rn(v0, v1);
            }
        }
    }
}

// ---------------- pooling (both branches, count fused; batch sorted) ----------------
__global__ void pool_c(const __half* __restrict__ x3a, const int* __restrict__ ba,
                       float* __restrict__ pa, float* __restrict__ ca, int N0, int blocks0,
                       const __half* __restrict__ x3b, const int* __restrict__ bb,
                       float* __restrict__ pb, float* __restrict__ cb, int N1) {
    const __half* x3; const int* batch; float* pool; float* cnt; int N, blk;
    if ((int)blockIdx.x < blocks0) { x3 = x3a; batch = ba; pool = pa; cnt = ca; N = N0; blk = blockIdx.x; }
    else { x3 = x3b; batch = bb; pool = pb; cnt = cb; N = N1; blk = blockIdx.x - blocks0; }
    int t = threadIdx.x;   // 0..191
    int r0 = blk * 256;
    int rend = r0 + 256; if (rend > N) rend = N;
    if (r0 >= N) return;
    int cur = batch[r0];
    float acc = 0.f, cacc = 0.f;
    for (int i = r0; i < rend; i++) {
        int b = batch[i];
        if (b != cur) {
            atomicAdd(&pool[cur * 192 + t], acc);
            if (t == 0) atomicAdd(&cnt[cur], cacc);
            acc = 0.f; cacc = 0.f; cur = b;
        }
        float v = __half2float(x3[(size_t)i * 384 + 192 + t]);
        v = (v > 0.f) ? v : expm1f(v);
        acc += v; cacc += 1.f;
    }
    atomicAdd(&pool[cur * 192 + t], acc);
    if (t == 0) atomicAdd(&cnt[cur], cacc);
}

// ---------------- final MLP: 8 blocks (one per batch row), 448->600->256->64 ----------------
__global__ void mlp_k8(const float* __restrict__ point,
                       const float* __restrict__ l1W, const float* __restrict__ l1b,
                       const float* __restrict__ l2W, const float* __restrict__ l2b,
                       const float* __restrict__ l3W, const float* __restrict__ l3b,
                       const float* __restrict__ pool, const float* __restrict__ cnt,
                       float* __restrict__ out) {
    __shared__ float in[448];
    __shared__ float h1[600];
    __shared__ float h2[256];
    int r = blockIdx.x;
    int t = threadIdx.x;

    for (int f = t; f < 448; f += blockDim.x) {
        float v;
        if (f < 192)       v = pool[r * 192 + f] / fmaxf(cnt[r], 1.f);
        else if (f < 384)  v = pool[1536 + r * 192 + (f - 192)] / fmaxf(cnt[8 + r], 1.f);
        else               v = point[r * 64 + (f - 384)];
        in[f] = v;
    }
    __syncthreads();

    if (t < 600) {
        float acc = l1b[t];
        const float4* w = (const float4*)(l1W + t * 448);
        #pragma unroll 4
        for (int f = 0; f < 112; f++) {
            float4 wv = w[f];
            const float4 iv = *(const float4*)&in[f * 4];
            acc += wv.x * iv.x + wv.y * iv.y + wv.z * iv.z + wv.w * iv.w;
        }
        h1[t] = fmaxf(acc, 0.f);
    }
    __syncthreads();

    if (t < 256) {
        float acc = l2b[t];
        const float4* w = (const float4*)(l2W + t * 600);
        #pragma unroll 4
        for (int f = 0; f < 150; f++) {
            float4 wv = w[f];
            const float4 iv = *(const float4*)&h1[f * 4];
            acc += wv.x * iv.x + wv.y * iv.y + wv.z * iv.z + wv.w * iv.w;
        }
        h2[t] = fmaxf(acc, 0.f);
    }
    __syncthreads();

    if (t < 64) {
        float acc = l3b[t];
        const float4* w = (const float4*)(l3W + t * 256);
        #pragma unroll 4
        for (int f = 0; f < 64; f++) {
            float4 wv = w[f];
            const float4 iv = *(const float4*)&h2[f * 4];
            acc += wv.x * iv.x + wv.y * iv.y + wv.z * iv.z + wv.w * iv.w;
        }
        out[r * 64 + t] = acc;
    }
}

extern "C" void kernel_launch(void* const* d_in, const int* in_sizes, int n_in,
                              void* d_out, int out_size) {
    float* scratch = nullptr;
    cudaGetSymbolAddress((void**)&scratch, d_scratch);
    cudaFuncSetAttribute(gemm_h<64, 128, 128, 0>, cudaFuncAttributeMaxDynamicSharedMemorySize, 65536);
    cudaFuncSetAttribute(gemm_h<128, 256, 256, 0>, cudaFuncAttributeMaxDynamicSharedMemorySize, 65536);
    cudaFuncSetAttribute(gemm_h<256, 256, 384, 1>, cudaFuncAttributeMaxDynamicSharedMemorySize, 65536);

    // Resolve input ordering (dict order vs reference-signature order)
    int GX, SX, PT, GEI, GB, SEI, SB, GW, SW, LW;
    if (n_in >= 4 && in_sizes[3] == 2 * EG) {
        GX = 0; SX = 1; PT = 2; GEI = 3; GB = 4; SEI = 5; SB = 6;
        GW = 7; SW = 16; LW = 25;
    } else {
        GX = 0; SX = 1; PT = 2; GW = 3; SW = 12; LW = 21;
        GEI = 27; GB = 28; SEI = 29; SB = 30;
    }

    const float* x0g = (const float*)d_in[GX];
    const float* x0s = (const float*)d_in[SX];
    const int* eig = (const int*)d_in[GEI];
    const int* eis = (const int*)d_in[SEI];
    const int* bag = (const int*)d_in[GB];
    const int* bas = (const int*)d_in[SB];

    __half* h0g  = (__half*)(scratch + H0_G);   __half* h0s  = (__half*)(scratch + H0_S);
    __half* aggg = (__half*)(scratch + AGG_G);  __half* aggs = (__half*)(scratch + AGG_S);
    __half* x1g  = (__half*)(scratch + X1_G);   __half* x1s  = (__half*)(scratch + X1_S);
    __half* x2g  = (__half*)(scratch + X2_G);   __half* x2s  = (__half*)(scratch + X2_S);
    __half* x3g  = (__half*)(scratch + X3_G);   __half* x3s  = (__half*)(scratch + X3_S);
    float* pool = scratch + POOL;
    float* cnt  = scratch + CNTO;
    int* degg = (int*)(scratch + DEG_G);   int* degs = (int*)(scratch + DEG_S);
    int* ptrg = (int*)(scratch + PTR_G);   int* ptrs = (int*)(scratch + PTR_S);
    int* filg = (int*)(scratch + FILL_G);  int* fils = (int*)(scratch + FILL_S);
    int* ssg  = (int*)(scratch + SS_G);    int* sss  = (int*)(scratch + SS_S);
    int* bsg  = (int*)(scratch + BS_G);    int* bss  = (int*)(scratch + BS_S);

    int b0 = (NG + 127) / 128, b1 = (NS + 127) / 128;
    int nbg = (NG + 255) / 256, nbs = (NS + 255) / 256;

    // ---- init: zero(pool+cnt+deg) + fp16 convert of both inputs, one launch ----
    {
        int nz4 = 15777;
        int n2a = NG * 32, n2b = NS * 32;
        int tot = nz4 + n2a + n2b;
        init_k<<<(tot + 255) / 256, 256>>>(scratch + POOL, nz4, x0g, h0g, n2a, x0s, h0s, n2b);
    }

    // ---- build CSR (once; shared by all three layers) ----
    {
        int tot = EG + ES;
        hist_c<<<(tot + 255) / 256, 256>>>(eig, EG, degg, eis, ES, degs);
        scan_blk<<<nbg + nbs, 256>>>(degg, ptrg, bsg, NG, nbg, degs, ptrs, bss, NS);
        scan_fin<<<(NG + NS + 2 + 255) / 256, 256>>>(ptrg, filg, bsg, NG, nbg,
                                                     ptrs, fils, bss, NS, nbs);
        fill_c<<<(tot + 255) / 256, 256>>>(eig, EG, filg, ssg, eis, ES, fils, sss);
    }

    // ---- layer 1: c=64 -> o=128, K=128
    {
        int tot = (NG + NS) * 8;
        gather_h<64, 3><<<(tot + 255) / 256, 256>>>(h0g, ptrg, ssg, aggg, NG,
                                                    h0s, ptrs, sss, aggs, NS);
        size_t smem = (size_t)(64 * 136 + 2 * 128 * 40) * 2;
        gemm_h<64, 128, 128, 0><<<dim3(2, b0 + b1), 256, smem>>>(
            aggg, h0g, (const float*)d_in[GW + 0], (const float*)d_in[GW + 1],
            (const float*)d_in[GW + 2], x1g, NG,
            aggs, h0s, (const float*)d_in[SW + 0], (const float*)d_in[SW + 1],
            (const float*)d_in[SW + 2], x1s, NS, b0);
    }
    // ---- layer 2: c=128 -> o=256, K=256
    {
        int tot = (NG + NS) * 16;
        gather_h<128, 4><<<(tot + 255) / 256, 256>>>(x1g, ptrg, ssg, aggg, NG,
                                                     x1s, ptrs, sss, aggs, NS);
        size_t smem = (size_t)(64 * 264 + 2 * 128 * 40) * 2;
        gemm_h<128, 256, 256, 0><<<dim3(4, b0 + b1), 256, smem>>>(
            aggg, x1g, (const float*)d_in[GW + 3], (const float*)d_in[GW + 4],
            (const float*)d_in[GW + 5], x2g, NG,
            aggs, x1s, (const float*)d_in[SW + 3], (const float*)d_in[SW + 4],
            (const float*)d_in[SW + 5], x2s, NS, b0);
    }
    // ---- layer 3: GEMM first (linearity swap), then width-192 CSR gather, then pool
    {
        size_t smem = (size_t)(64 * 264 + 2 * 128 * 40) * 2;
        gemm_h<256, 256, 384, 1><<<dim3(6, b0 + b1), 256, smem>>>(
            x2g, x2g, (const float*)d_in[GW + 6], (const float*)d_in[GW + 7],
            (const float*)d_in[GW + 8], x3g, NG,
            x2s, x2s, (const float*)d_in[SW + 6], (const float*)d_in[SW + 7],
            (const float*)d_in[SW + 8], x3s, NS, b0);
        int tot = (NG + NS) * 24;
        gather3_h<<<(tot + 255) / 256, 256>>>(ptrg, ssg, x3g, NG, ptrs, sss, x3s, NS);
        int pb0 = (NG + 255) / 256, pb1 = (NS + 255) / 256;
        pool_c<<<pb0 + pb1, 192>>>(x3g, bag, pool, cnt, NG, pb0,
                                   x3s, bas, pool + 1536, cnt + 8, NS);
    }

    mlp_k8<<<8, 640>>>((const float*)d_in[PT],
                       (const float*)d_in[LW + 0], (const float*)d_in[LW + 1],
                       (const float*)d_in[LW + 2], (const float*)d_in[LW + 3],
                       (const float*)d_in[LW + 4], (const float*)d_in[LW + 5],
                       pool, cnt, (float*)d_out);
}